// round 4
// baseline (speedup 1.0000x reference)
#include <cuda_runtime.h>

// Problem constants (fixed by the reference setup_inputs)
#define BB     32
#define NN     4096
#define FDIM   128
#define LDH    200            // L*DH floats per agent in hist_feat
#define KK     8
#define APB    256            // agents per block (== blockDim)
#define CHUNKS 16             // blocks per batch
#define CANDS  (CHUNKS * KK)  // 128 candidate keys per batch

#define KEY_MAX 0xFFFFFFFFFFFFFFFFull
#define FULL    0xffffffffu

__device__ unsigned long long g_cand[BB * CANDS];
__device__ int g_counter[BB];   // zero-init; finisher resets to 0 each call

static __device__ __forceinline__ unsigned long long umin64(unsigned long long a,
                                                            unsigned long long b) {
    return a < b ? a : b;
}

// ---------------------------------------------------------------------------
// Fused kernel. One warp scores 32 agents in 8 steps of 4 agents; each agent
// is reduced by an 8-lane sub-group (3-step butterfly). Loads stay fully
// coalesced (each LDG.128 = 4 rows x one whole 128B line).
// Keys: (score_bits << 32) | (j-1) -> min-order = (score asc, index asc),
// matching lax.top_k(-score) tie-break semantics.
// ---------------------------------------------------------------------------
__global__ __launch_bounds__(APB)
void fused_kernel(const float* __restrict__ x,   // (B, N, FDIM)
                  const float* __restrict__ hf,  // (B, N, L, DH)
                  const float* __restrict__ he,  // (B, N, FDIM)
                  unsigned long long* __restrict__ cand,
                  float* __restrict__ out)
{
    const int b     = blockIdx.x / CHUNKS;
    const int chunk = blockIdx.x % CHUNKS;
    const int t     = threadIdx.x;
    const int warp  = t >> 5;
    const int lane  = t & 31;
    const int s     = lane & 7;    // slice within 8-lane group
    const int a     = lane >> 3;   // agent-in-group (0..3)

    __shared__ float4 scx[FDIM / 4];   // center x row
    __shared__ float4 scv[FDIM / 4];   // center embed row
    __shared__ unsigned long long skeys[8 * KK];
    __shared__ int s_last;
    __shared__ int sel_idx[KK];

    // stage center rows
    if (t < FDIM / 4) {
        scx[t] = ((const float4*)(x  + (size_t)b * NN * FDIM))[t];
        scv[t] = ((const float4*)(he + (size_t)b * NN * FDIM))[t];
    }
    __syncthreads();

    // ---- center embed norm: per-lane slice + 3-step butterfly ----
    float vv = 0.0f;
    #pragma unroll
    for (int q = 0; q < 4; q++) {
        float4 V = scv[s + 8 * q];
        vv += V.x*V.x + V.y*V.y + V.z*V.z + V.w*V.w;
    }
    #pragma unroll
    for (int off = 1; off < 8; off <<= 1)
        vv += __shfl_xor_sync(FULL, vv, off);
    const float vnm = fmaxf(sqrtf(vv), 1e-8f);

    // ---- center direction (uniform) ----
    const float* h0 = hf + (size_t)b * NN * LDH;
    float2 p048 = *(const float2*)(h0 + 192);
    float2 p049 = *(const float2*)(h0 + 196);
    float d0x = p049.x - p048.x, d0y = p049.y - p048.y;
    float inv0 = 1.0f / fmaxf(sqrtf(d0x*d0x + d0y*d0y), 1e-12f);
    float cdx = d0x * inv0 + 1e-8f;
    float cdy = d0y * inv0 + 1e-8f;
    const float cnorm = fmaxf(sqrtf(cdx*cdx + cdy*cdy), 1e-8f);

    // ---- per-lane velocity similarity: lane l <-> agent j0+l ----
    const int j0 = 1 + chunk * APB + warp * 32;
    float vsim;
    {
        int jl = j0 + lane;
        int jls = jl < NN ? jl : NN - 1;
        const float* hj = hf + ((size_t)b * NN + jls) * LDH;
        float2 a48 = *(const float2*)(hj + 192);
        float2 a49 = *(const float2*)(hj + 196);
        float djx = a49.x - a48.x, djy = a49.y - a48.y;
        float invj = 1.0f / fmaxf(sqrtf(djx*djx + djy*djy), 1e-12f);
        float odx = djx * invj + 1e-8f;
        float ody = djy * invj + 1e-8f;
        float vnum = odx*cdx + ody*cdy;
        float vden = fmaxf(sqrtf(odx*odx + ody*ody), 1e-8f) * cnorm;
        vsim = vnum / vden;
    }

    // ---- main loop: 8 steps x 4 agents ----
    unsigned long long mykey = KEY_MAX;   // lane l holds key of agent j0+l

    #pragma unroll 2
    for (int g = 0; g < 8; g++) {
        int j  = j0 + 4 * g + a;
        int js = j < NN ? j : NN - 1;
        const float4* __restrict__ xr = (const float4*)(x  + ((size_t)b * NN + js) * FDIM);
        const float4* __restrict__ ur = (const float4*)(he + ((size_t)b * NN + js) * FDIM);

        float d2 = 0.0f, tn = 0.0f, uu = 0.0f;
        #pragma unroll
        for (int q = 0; q < 4; q++) {
            float4 A = xr[s + 8 * q];
            float4 U = ur[s + 8 * q];
            float4 C = scx[s + 8 * q];
            float4 V = scv[s + 8 * q];
            float ex = A.x - C.x, ey = A.y - C.y, ez = A.z - C.z, ew = A.w - C.w;
            d2 += ex*ex + ey*ey + ez*ez + ew*ew;
            tn += U.x*V.x + U.y*V.y + U.z*V.z + U.w*V.w;
            uu += U.x*U.x + U.y*U.y + U.z*U.z + U.w*U.w;
        }
        // 3-step butterfly within the 8-lane group
        #pragma unroll
        for (int off = 1; off < 8; off <<= 1) {
            d2 += __shfl_xor_sync(FULL, d2, off);
            tn += __shfl_xor_sync(FULL, tn, off);
            uu += __shfl_xor_sync(FULL, uu, off);
        }

        // vsim of this group's agent (agent 4g+a lives on lane 4g+a)
        float vs = __shfl_sync(FULL, vsim, 4 * g + a);

        float tsim  = tn / (fmaxf(sqrtf(uu), 1e-8f) * vnm);
        float score = 0.3f * sqrtf(d2)
                    + 0.5f * (1.0f - fmaxf(vs,   0.0f))
                    + 0.4f * (1.0f - fmaxf(tsim, 0.0f));
        score = fmaxf(score, 0.0f);   // keep bit-pattern order-preserving

        // deliver score of agent 4g+w&3 to lane w in [4g, 4g+4)
        float sc = __shfl_sync(FULL, score, 8 * (lane & 3));
        if ((lane >> 2) == g && (j0 + lane) < NN)
            mykey = ((unsigned long long)__float_as_uint(sc) << 32)
                  | (unsigned int)(j0 + lane - 1);
    }

    // ---- warp top-8: 8 rounds of 64-bit butterfly argmin ----
    unsigned long long sel = KEY_MAX;
    #pragma unroll
    for (int it = 0; it < KK; it++) {
        unsigned long long m = mykey;
        #pragma unroll
        for (int off = 16; off > 0; off >>= 1)
            m = umin64(m, __shfl_xor_sync(FULL, m, off));
        if (mykey == m) mykey = KEY_MAX;   // keys unique -> single winner
        if (lane == it) sel = m;
    }
    if (lane < KK) skeys[warp * KK + lane] = sel;
    __syncthreads();

    // ---- block merge: warp 0 reduces 64 -> 8, writes candidates ----
    if (warp == 0) {
        unsigned long long k0 = skeys[lane];
        unsigned long long k1 = skeys[lane + 32];
        unsigned long long sel2 = KEY_MAX;
        #pragma unroll
        for (int it = 0; it < KK; it++) {
            unsigned long long m = umin64(k0, k1);
            #pragma unroll
            for (int off = 16; off > 0; off >>= 1)
                m = umin64(m, __shfl_xor_sync(FULL, m, off));
            if (k0 == m) k0 = KEY_MAX;
            else if (k1 == m) k1 = KEY_MAX;
            if (lane == it) sel2 = m;
        }
        if (lane < KK)
            cand[((size_t)b * CHUNKS + chunk) * KK + lane] = sel2;
    }

    // ---- arrival protocol: last block of this batch merges + gathers ----
    __threadfence();
    __syncthreads();
    if (t == 0) {
        int old = atomicAdd(&g_counter[b], 1);
        s_last = (old == CHUNKS - 1) ? 1 : 0;
    }
    __syncthreads();
    if (!s_last) return;

    __threadfence();   // acquire: see all other blocks' cand writes

    if (t < 32) {
        unsigned long long k[4];
        #pragma unroll
        for (int q = 0; q < 4; q++)
            k[q] = cand[(size_t)b * CANDS + q * 32 + t];

        #pragma unroll
        for (int it = 0; it < KK; it++) {
            unsigned long long m = umin64(umin64(k[0], k[1]), umin64(k[2], k[3]));
            #pragma unroll
            for (int off = 16; off > 0; off >>= 1)
                m = umin64(m, __shfl_xor_sync(FULL, m, off));
            #pragma unroll
            for (int q = 0; q < 4; q++)
                if (k[q] == m) k[q] = KEY_MAX;
            if (t == 0) sel_idx[it] = (int)(unsigned int)(m & 0xFFFFFFFFu);
        }
        if (t == 0) g_counter[b] = 0;   // reset for next graph replay
    }
    __syncthreads();

    // gather: 256 threads = 8 rows x 32 lanes of float4
    {
        const int kk  = t >> 5;
        const int l   = t & 31;
        const int idx = sel_idx[kk];
        float4 val = ((const float4*)(x + ((size_t)b * NN + idx + 1) * FDIM))[l];
        ((float4*)(out + ((size_t)b * KK + kk) * FDIM))[l] = val;
    }
    if (t < KK)
        out[(size_t)BB * KK * FDIM + b * KK + t] = (float)sel_idx[t];
}

extern "C" void kernel_launch(void* const* d_in, const int* in_sizes, int n_in,
                              void* d_out, int out_size)
{
    const float* x  = (const float*)d_in[0];   // (B, N, FDIM) f32
    const float* hf = (const float*)d_in[1];   // (B, N, L, DH) f32
    const float* he = (const float*)d_in[2];   // (B, N, FDIM) f32
    float* out = (float*)d_out;

    unsigned long long* cand;
    cudaGetSymbolAddress((void**)&cand, g_cand);

    fused_kernel<<<BB * CHUNKS, APB>>>(x, hf, he, cand, out);
}

// round 5
// speedup vs baseline: 1.3197x; 1.3197x over previous
#include <cuda_runtime.h>
#include <cstdint>

// Problem constants (fixed by the reference setup_inputs)
#define BB     32
#define NN     4096
#define FDIM   128
#define LDH    200            // L*DH floats per agent in hist_feat
#define KK     8
#define APB    256            // agents per block (== blockDim)
#define CHUNKS 16             // blocks per batch
#define CANDS  (CHUNKS * KK)  // 128 candidate keys per batch

#define CH       16                 // columns per pipeline chunk
#define NCH      (FDIM / CH)        // 8 chunks
#define RSTRIDE  5                  // float4s per staged row (20 floats, padded)
#define STAGE_F4 (APB * RSTRIDE)    // 1280 float4 per array per stage
// dyn layout: [stage0 x][stage0 he][stage1 x][stage1 he][scx 32][scv 32]
#define SMEM_F4    (4 * STAGE_F4 + 64)
#define SMEM_BYTES (SMEM_F4 * 16)   // 82944 B

#define KEY_MAX 0xFFFFFFFFFFFFFFFFull
#define FULL    0xffffffffu

__device__ unsigned long long g_cand[BB * CANDS];
__device__ int g_counter[BB];   // zero-init; finisher resets to 0 each call

static __device__ __forceinline__ unsigned long long umin64(unsigned long long a,
                                                            unsigned long long b) {
    return a < b ? a : b;
}

static __device__ __forceinline__ void cp_async16(uint32_t saddr, const void* gptr) {
    asm volatile("cp.async.cg.shared.global [%0], [%1], 16;" :: "r"(saddr), "l"(gptr));
}

// ---------------------------------------------------------------------------
// Fused kernel: cp.async double-buffered row staging, thread-per-agent
// scoring (no shuffles in hot loop), hierarchical top-8, fused finisher.
// Keys: (score_bits << 32) | (j-1) -> min-order = (score asc, index asc),
// matching lax.top_k(-score) tie-break semantics.
// ---------------------------------------------------------------------------
__global__ __launch_bounds__(APB)
void fused_kernel(const float* __restrict__ x,   // (B, N, FDIM)
                  const float* __restrict__ hf,  // (B, N, L, DH)
                  const float* __restrict__ he,  // (B, N, FDIM)
                  unsigned long long* __restrict__ cand,
                  float* __restrict__ out)
{
    const int b        = blockIdx.x / CHUNKS;
    const int blkchunk = blockIdx.x % CHUNKS;
    const int t        = threadIdx.x;
    const int warp     = t >> 5;
    const int lane     = t & 31;
    const int j0       = 1 + blkchunk * APB;   // first agent row of this block

    extern __shared__ float4 dyn[];
    float4* scx = dyn + 4 * STAGE_F4;   // center x row (32 f4)
    float4* scv = scx + 32;             // center embed row (32 f4)
    const uint32_t dynbase = (uint32_t)__cvta_generic_to_shared(dyn);

    __shared__ unsigned long long skeys[8 * KK];
    __shared__ int s_last;
    __shared__ int sel_idx[KK];

    const float4* __restrict__ xb = (const float4*)(x  + (size_t)b * NN * FDIM); // row stride 32 f4
    const float4* __restrict__ ub = (const float4*)(he + (size_t)b * NN * FDIM);

    // ---- stage center rows (visible after first __syncthreads) ----
    if (t < 32) { scx[t] = xb[t]; scv[t] = ub[t]; }

    // ---- per-thread agent id ----
    const int  j     = j0 + t;           // 1 .. 4096
    const bool valid = (j < NN);
    const int  js    = valid ? j : NN - 1;

    // ---- center direction + per-thread velocity similarity (early, overlaps) ----
    float vsim;
    {
        const float* h0 = hf + (size_t)b * NN * LDH;
        float2 p048 = *(const float2*)(h0 + 192);
        float2 p049 = *(const float2*)(h0 + 196);
        const float* hj = hf + ((size_t)b * NN + js) * LDH;
        float2 a48 = *(const float2*)(hj + 192);
        float2 a49 = *(const float2*)(hj + 196);

        float d0x = p049.x - p048.x, d0y = p049.y - p048.y;
        float inv0 = 1.0f / fmaxf(sqrtf(d0x*d0x + d0y*d0y), 1e-12f);
        float cdx = d0x * inv0 + 1e-8f;
        float cdy = d0y * inv0 + 1e-8f;
        float cnorm = fmaxf(sqrtf(cdx*cdx + cdy*cdy), 1e-8f);

        float djx = a49.x - a48.x, djy = a49.y - a48.y;
        float invj = 1.0f / fmaxf(sqrtf(djx*djx + djy*djy), 1e-12f);
        float odx = djx * invj + 1e-8f;
        float ody = djy * invj + 1e-8f;
        float vnum = odx*cdx + ody*cdy;
        float vden = fmaxf(sqrtf(odx*odx + ody*ody), 1e-8f) * cnorm;
        vsim = vnum / vden;
    }

    // ---- staging issue: chunk cc (cols [16cc,16cc+16)) into stage st ----
    auto issue = [&](int cc, int st) {
        const uint32_t sb = dynbase + (uint32_t)(st * 2 * STAGE_F4) * 16u;
        #pragma unroll
        for (int q = 0; q < 4; q++) {
            int i   = t + APB * q;            // 0..1023 f4 slots, lane-consecutive
            int row = i >> 2;
            int q4  = i & 3;
            int gr  = j0 + row; if (gr > NN - 1) gr = NN - 1;
            const float4* gx = xb + (size_t)gr * 32 + cc * 4 + q4;
            const float4* gu = ub + (size_t)gr * 32 + cc * 4 + q4;
            uint32_t soff = (uint32_t)(row * RSTRIDE + q4) * 16u;
            cp_async16(sb + soff, gx);
            cp_async16(sb + (uint32_t)STAGE_F4 * 16u + soff, gu);
        }
        asm volatile("cp.async.commit_group;");
    };

    // ---- pipelined main loop ----
    float d2 = 0.0f, tn = 0.0f, uu = 0.0f, vv = 0.0f;

    issue(0, 0);
    #pragma unroll
    for (int cc = 0; cc < NCH; cc++) {
        if (cc + 1 < NCH) {
            issue(cc + 1, (cc + 1) & 1);
            asm volatile("cp.async.wait_group 1;");
        } else {
            asm volatile("cp.async.wait_group 0;");
        }
        __syncthreads();   // chunk cc staged everywhere (+ centers on cc==0)

        const float4* bx = dyn + ((cc & 1) * 2) * STAGE_F4 + t * RSTRIDE;
        const float4* bu = bx + STAGE_F4;
        #pragma unroll
        for (int q = 0; q < 4; q++) {
            float4 A = bx[q];
            float4 U = bu[q];
            float4 C = scx[cc * 4 + q];
            float4 V = scv[cc * 4 + q];
            float ex = A.x - C.x, ey = A.y - C.y, ez = A.z - C.z, ew = A.w - C.w;
            d2 += ex*ex + ey*ey + ez*ez + ew*ew;
            tn += U.x*V.x + U.y*V.y + U.z*V.z + U.w*V.w;
            uu += U.x*U.x + U.y*U.y + U.z*U.z + U.w*U.w;
            vv += V.x*V.x + V.y*V.y + V.z*V.z + V.w*V.w;
        }
        __syncthreads();   // all reads done before this stage is re-filled
    }

    // ---- score ----
    const float vnm  = fmaxf(sqrtf(vv), 1e-8f);
    float tsim  = tn / (fmaxf(sqrtf(uu), 1e-8f) * vnm);
    float score = 0.3f * sqrtf(d2)
                + 0.5f * (1.0f - fmaxf(vsim, 0.0f))
                + 0.4f * (1.0f - fmaxf(tsim, 0.0f));
    score = fmaxf(score, 0.0f);   // keep float bit-pattern order-preserving

    unsigned long long mykey = valid
        ? (((unsigned long long)__float_as_uint(score) << 32) | (unsigned int)(j - 1))
        : KEY_MAX;

    // ---- warp top-8: 8 rounds of 64-bit butterfly argmin ----
    unsigned long long sel = KEY_MAX;
    #pragma unroll
    for (int it = 0; it < KK; it++) {
        unsigned long long m = mykey;
        #pragma unroll
        for (int off = 16; off > 0; off >>= 1)
            m = umin64(m, __shfl_xor_sync(FULL, m, off));
        if (mykey == m) mykey = KEY_MAX;   // keys unique -> single winner
        if (lane == it) sel = m;
    }
    if (lane < KK) skeys[warp * KK + lane] = sel;
    __syncthreads();

    // ---- block merge: warp 0 reduces 64 -> 8, writes candidates ----
    if (warp == 0) {
        unsigned long long k0 = skeys[lane];
        unsigned long long k1 = skeys[lane + 32];
        unsigned long long sel2 = KEY_MAX;
        #pragma unroll
        for (int it = 0; it < KK; it++) {
            unsigned long long m = umin64(k0, k1);
            #pragma unroll
            for (int off = 16; off > 0; off >>= 1)
                m = umin64(m, __shfl_xor_sync(FULL, m, off));
            if (k0 == m) k0 = KEY_MAX;
            else if (k1 == m) k1 = KEY_MAX;
            if (lane == it) sel2 = m;
        }
        if (lane < KK)
            cand[((size_t)b * CHUNKS + blkchunk) * KK + lane] = sel2;
    }

    // ---- arrival protocol: last block of this batch merges + gathers ----
    __threadfence();
    __syncthreads();
    if (t == 0) {
        int old = atomicAdd(&g_counter[b], 1);
        s_last = (old == CHUNKS - 1) ? 1 : 0;
    }
    __syncthreads();
    if (!s_last) return;

    __threadfence();   // acquire: see all other blocks' cand writes

    if (t < 32) {
        unsigned long long k[4];
        #pragma unroll
        for (int q = 0; q < 4; q++)
            k[q] = cand[(size_t)b * CANDS + q * 32 + t];

        #pragma unroll
        for (int it = 0; it < KK; it++) {
            unsigned long long m = umin64(umin64(k[0], k[1]), umin64(k[2], k[3]));
            #pragma unroll
            for (int off = 16; off > 0; off >>= 1)
                m = umin64(m, __shfl_xor_sync(FULL, m, off));
            #pragma unroll
            for (int q = 0; q < 4; q++)
                if (k[q] == m) k[q] = KEY_MAX;
            if (t == 0) sel_idx[it] = (int)(unsigned int)(m & 0xFFFFFFFFu);
        }
        if (t == 0) g_counter[b] = 0;   // reset for next graph replay
    }
    __syncthreads();

    // gather: 256 threads = 8 rows x 32 lanes of float4
    {
        const int kk  = t >> 5;
        const int l   = t & 31;
        const int idx = sel_idx[kk];
        float4 val = xb[(size_t)(idx + 1) * 32 + l];
        ((float4*)(out + ((size_t)b * KK + kk) * FDIM))[l] = val;
    }
    if (t < KK)
        out[(size_t)BB * KK * FDIM + b * KK + t] = (float)sel_idx[t];
}

extern "C" void kernel_launch(void* const* d_in, const int* in_sizes, int n_in,
                              void* d_out, int out_size)
{
    const float* x  = (const float*)d_in[0];   // (B, N, FDIM) f32
    const float* hf = (const float*)d_in[1];   // (B, N, L, DH) f32
    const float* he = (const float*)d_in[2];   // (B, N, FDIM) f32
    float* out = (float*)d_out;

    unsigned long long* cand;
    cudaGetSymbolAddress((void**)&cand, g_cand);

    cudaFuncSetAttribute(fused_kernel,
                         cudaFuncAttributeMaxDynamicSharedMemorySize, SMEM_BYTES);

    fused_kernel<<<BB * CHUNKS, APB, SMEM_BYTES>>>(x, hf, he, cand, out);
}